// round 1
// baseline (speedup 1.0000x reference)
#include <cuda_runtime.h>
#include <cuda_bf16.h>

// Problem constants
#define Bsz   128
#define Gsz   100
#define Lz    16
#define HL    512
#define Dd    64
#define OUTSZ 8450   // 64+1 + 4096+64 + 4096+64 + 64+1

// wab row layout (reference order):
// w0 [0,64), b0 [64], w1 [65,4161), b1 [4161,4225), w2 [4225,8321), b2 [8321,8385),
// w3 [8385,8449), b3 [8449]

// Scratch (device globals: no allocation allowed)
__device__ float g_h0[Bsz * HL];
__device__ float g_h1[Bsz * HL];
__device__ float g_h2[Bsz * HL];
__device__ float g_wab[Bsz * OUTSZ];

__device__ __forceinline__ float leaky(float v) { return v > 0.f ? v : 0.01f * v; }

// ---------------------------------------------------------------------------
// Kernel 1: h0 = leaky(z @ hW0 + hb0)    (128 x 512, K = 16)
// ---------------------------------------------------------------------------
__global__ void k_h0(const float* __restrict__ z, const float* __restrict__ hW0,
                     const float* __restrict__ hb0) {
    __shared__ float zs[Lz];
    int b = blockIdx.x;
    int j = threadIdx.x;
    if (j < Lz) zs[j] = z[b * Lz + j];
    __syncthreads();
    float acc = hb0[j];
#pragma unroll
    for (int i = 0; i < Lz; i++) acc = fmaf(zs[i], hW0[i * HL + j], acc);
    g_h0[b * HL + j] = leaky(acc);
}

// ---------------------------------------------------------------------------
// Generic GEMM: C(128,N) = act(A(128,512) @ W(512,N) + bias)
// BM=128 (full M), BK=32, 256 threads. Thread tile TM x TN.
// ---------------------------------------------------------------------------
template <int BN, int TM, int TN, bool LEAKY>
__global__ void gemm_kernel(const float* __restrict__ A, const float* __restrict__ W,
                            const float* __restrict__ bias, float* __restrict__ C,
                            int N) {
    constexpr int BM = 128;
    constexpr int BK = 32;
    constexpr int K  = 512;
    constexpr int CT = BN / TN;           // threads along N
    // RT = BM / TM; CT * RT must be 256

    __shared__ float As[BK][132];         // [k][m], padded row (132*4 % 16 == 0)
    __shared__ float Bs[BK][BN];

    const int tid  = threadIdx.x;
    const int n0   = blockIdx.x * BN;
    const int tcol = tid % CT;
    const int trow = tid / CT;

    float acc[TM][TN];
#pragma unroll
    for (int i = 0; i < TM; i++)
#pragma unroll
        for (int j = 0; j < TN; j++) acc[i][j] = 0.f;

    for (int k0 = 0; k0 < K; k0 += BK) {
        // load A tile (transpose into As[k][m]); float4 along k, coalesced
        {
            int c = tid % 8;              // k-group (4 floats each)
            int r = tid / 8;              // 0..31
#pragma unroll
            for (int rr = 0; rr < 4; rr++) {
                int m = r + rr * 32;
                float4 av = *reinterpret_cast<const float4*>(A + m * K + k0 + c * 4);
                As[c * 4 + 0][m] = av.x;
                As[c * 4 + 1][m] = av.y;
                As[c * 4 + 2][m] = av.z;
                As[c * 4 + 3][m] = av.w;
            }
        }
        // load B tile
#pragma unroll
        for (int u = 0; u < (BK * BN + 255) / 256; u++) {
            int idx = tid + u * 256;
            if (idx < BK * BN) {
                int kk = idx / BN, n = idx % BN;
                int gn = n0 + n;
                Bs[kk][n] = (gn < N) ? W[(k0 + kk) * N + gn] : 0.f;
            }
        }
        __syncthreads();

#pragma unroll
        for (int kk = 0; kk < BK; kk++) {
            float a[TM], bv[TN];
#pragma unroll
            for (int i = 0; i < TM; i += 4) {
                float4 v = *reinterpret_cast<const float4*>(&As[kk][trow * TM + i]);
                a[i] = v.x; a[i + 1] = v.y; a[i + 2] = v.z; a[i + 3] = v.w;
            }
#pragma unroll
            for (int j = 0; j < TN; j++) bv[j] = Bs[kk][tcol * TN + j];
#pragma unroll
            for (int i = 0; i < TM; i++)
#pragma unroll
                for (int j = 0; j < TN; j++) acc[i][j] = fmaf(a[i], bv[j], acc[i][j]);
        }
        __syncthreads();
    }

#pragma unroll
    for (int i = 0; i < TM; i++) {
        int m = trow * TM + i;
#pragma unroll
        for (int j = 0; j < TN; j++) {
            int gn = n0 + tcol * TN + j;
            if (gn < N) {
                float v = acc[i][j] + bias[gn];
                if (LEAKY) v = leaky(v);
                C[m * N + gn] = v;
            }
        }
    }
}

// ---------------------------------------------------------------------------
// Decoder: one block per b, one thread per g. wab[b] staged into smem
// (rearranged so weight matrices are 16B-aligned). All weight LDS are
// warp-broadcast; per-thread activations live in padded smem rows.
// ---------------------------------------------------------------------------
// smem float layout:
#define SW1 0        // 4096
#define SW2 4096     // 4096
#define SW0 8192     // 64
#define SW3 8256     // 64
#define SB1 8320     // 64
#define SB2 8384     // 64
#define SB0 8448
#define SB3 8449
#define SX  8452     // per-thread activations: 128 rows, stride 65
#define XSTRIDE 65
#define DEC_SMEM_FLOATS (SX + 128 * XSTRIDE)
#define DEC_SMEM_BYTES  (DEC_SMEM_FLOATS * 4)

__device__ __forceinline__ void dec_layer(float* __restrict__ s, float* __restrict__ xs,
                                          int wbase, int bbase) {
    float acc[Dd];
#pragma unroll
    for (int j = 0; j < Dd; j++) acc[j] = s[bbase + j];
    for (int i = 0; i < Dd; i++) {
        float v = xs[i];
        const float4* wr = reinterpret_cast<const float4*>(&s[wbase + i * Dd]);
#pragma unroll
        for (int q = 0; q < Dd / 4; q++) {
            float4 w = wr[q];
            acc[4 * q + 0] = fmaf(v, w.x, acc[4 * q + 0]);
            acc[4 * q + 1] = fmaf(v, w.y, acc[4 * q + 1]);
            acc[4 * q + 2] = fmaf(v, w.z, acc[4 * q + 2]);
            acc[4 * q + 3] = fmaf(v, w.w, acc[4 * q + 3]);
        }
    }
#pragma unroll
    for (int j = 0; j < Dd; j++) xs[j] = __sinf(acc[j]);
}

__global__ void decoder_kernel(const float* __restrict__ log_P, float* __restrict__ out) {
    extern __shared__ float s[];
    const int b = blockIdx.x;
    const int tid = threadIdx.x;
    const float* gw = g_wab + b * OUTSZ;

    for (int i = tid; i < 4096; i += 128) s[SW1 + i] = gw[65 + i];
    for (int i = tid; i < 4096; i += 128) s[SW2 + i] = gw[4225 + i];
    if (tid < 64) {
        s[SW0 + tid] = gw[tid];
        s[SW3 + tid] = gw[8385 + tid];
        s[SB1 + tid] = gw[4161 + tid];
        s[SB2 + tid] = gw[8321 + tid];
    }
    if (tid == 0) { s[SB0] = gw[64]; s[SB3] = gw[8449]; }
    __syncthreads();

    if (tid < Gsz) {
        float x = log_P[b * Gsz + tid] * (1.f / 3.f);   // (log_P - 0) / 3
        float* xs = &s[SX + tid * XSTRIDE];
        float b0 = s[SB0];
#pragma unroll
        for (int j = 0; j < Dd; j++)
            xs[j] = __sinf(30.f * fmaf(x, s[SW0 + j], b0));

        dec_layer(s, xs, SW1, SB1);
        dec_layer(s, xs, SW2, SB2);

        float accf = s[SB3];
#pragma unroll
        for (int i = 0; i < Dd; i++) accf = fmaf(xs[i], s[SW3 + i], accf);
        out[b * Gsz + tid] = fmaf(accf, 500.f, 1500.f);
    }
}

// ---------------------------------------------------------------------------
// Launch
// ---------------------------------------------------------------------------
extern "C" void kernel_launch(void* const* d_in, const int* in_sizes, int n_in,
                              void* d_out, int out_size) {
    const float* z     = (const float*)d_in[0];
    const float* log_P = (const float*)d_in[1];
    const float* hW0   = (const float*)d_in[2];
    const float* hb0   = (const float*)d_in[3];
    const float* hW1   = (const float*)d_in[4];
    const float* hb1   = (const float*)d_in[5];
    const float* hW2   = (const float*)d_in[6];
    const float* hb2   = (const float*)d_in[7];
    const float* hWo   = (const float*)d_in[8];
    const float* hbo   = (const float*)d_in[9];
    float* out = (float*)d_out;

    float *h0p, *h1p, *h2p, *wabp;
    cudaGetSymbolAddress((void**)&h0p, g_h0);
    cudaGetSymbolAddress((void**)&h1p, g_h1);
    cudaGetSymbolAddress((void**)&h2p, g_h2);
    cudaGetSymbolAddress((void**)&wabp, g_wab);

    cudaFuncSetAttribute(decoder_kernel, cudaFuncAttributeMaxDynamicSharedMemorySize,
                         DEC_SMEM_BYTES);

    k_h0<<<Bsz, HL>>>(z, hW0, hb0);
    gemm_kernel<8, 4, 1, true><<<HL / 8, 256>>>(h0p, hW1, hb1, h1p, HL);
    gemm_kernel<8, 4, 1, true><<<HL / 8, 256>>>(h1p, hW2, hb2, h2p, HL);
    gemm_kernel<32, 8, 2, false><<<(OUTSZ + 31) / 32, 256>>>(h2p, hWo, hbo, wabp, OUTSZ);
    decoder_kernel<<<Bsz, 128, DEC_SMEM_BYTES>>>(log_P, out);
}

// round 3
// speedup vs baseline: 1.3099x; 1.3099x over previous
#include <cuda_runtime.h>
#include <cuda_bf16.h>
#include <cstdint>

// Problem constants
#define Bsz   128
#define Gsz   100
#define Lz    16
#define HL    512
#define Dd    64
#define OUTSZ 8450   // 64+1 + 4096+64 + 4096+64 + 64+1

typedef unsigned long long ULL;

// Scratch (device globals: no allocation allowed)
__device__ float g_h0[Bsz * HL];
__device__ float g_h1[Bsz * HL];
__device__ float g_h2t[HL * Bsz];       // h2 stored TRANSPOSED: [k][m]
__device__ float g_wab[Bsz * OUTSZ];

__device__ __forceinline__ float leaky(float v) { return v > 0.f ? v : 0.01f * v; }

// ---- packed fp32x2 helpers (sm_100 packed dual-FMA; bit-exact IEEE fp32) ----
__device__ __forceinline__ ULL pack2(float lo, float hi) {
    ULL r; asm("mov.b64 %0, {%1, %2};" : "=l"(r) : "f"(lo), "f"(hi)); return r;
}
__device__ __forceinline__ ULL dup2(float x) {
    ULL r; asm("mov.b64 %0, {%1, %1};" : "=l"(r) : "f"(x)); return r;
}
__device__ __forceinline__ void unpack2(ULL v, float& lo, float& hi) {
    asm("mov.b64 {%0, %1}, %2;" : "=f"(lo), "=f"(hi) : "l"(v));
}
__device__ __forceinline__ void ffma2(ULL& acc, ULL a, ULL b) {
    asm("fma.rn.f32x2 %0, %1, %2, %0;" : "+l"(acc) : "l"(a), "l"(b));
}

// ---------------------------------------------------------------------------
// Kernel 1: h0 = leaky(z @ hW0 + hb0)    (128 x 512, K = 16)
// ---------------------------------------------------------------------------
__global__ void k_h0(const float* __restrict__ z, const float* __restrict__ hW0,
                     const float* __restrict__ hb0) {
    __shared__ float zs[Lz];
    int b = blockIdx.x;
    int j = threadIdx.x;
    if (j < Lz) zs[j] = z[b * Lz + j];
    __syncthreads();
    float acc = hb0[j];
#pragma unroll
    for (int i = 0; i < Lz; i++) acc = fmaf(zs[i], hW0[i * HL + j], acc);
    g_h0[b * HL + j] = leaky(acc);
}

// ---------------------------------------------------------------------------
// Hidden GEMM: C = leaky(A(128,512) @ W(512,512) + bias)
// BM=128, BN=8, BK=32, 256 threads, TM=4 (2 packed pairs), TN=1. Grid=64.
// TRANS: write C[n][128] (transposed) instead of C[m][512].
// ---------------------------------------------------------------------------
template <bool TRANS>
__global__ void __launch_bounds__(256) hidden_gemm(const float* __restrict__ A,
                                                   const float* __restrict__ W,
                                                   const float* __restrict__ bias,
                                                   float* __restrict__ C) {
    constexpr int BN = 8, BK = 32, K = 512;
    __shared__ float As[BK][132];   // [k][m], padded
    __shared__ float Bs[BK][BN];

    const int tid  = threadIdx.x;
    const int n0   = blockIdx.x * BN;
    const int tcol = tid % BN;       // 0..7
    const int trow = tid / BN;       // 0..31 (covers m in steps of TM=4)

    ULL acc0 = 0, acc1 = 0;

    for (int k0 = 0; k0 < K; k0 += BK) {
        // load A tile (transpose into As[k][m]); float4 along k
        {
            int c = tid % 8;              // k-group
            int r = tid / 8;              // 0..31
#pragma unroll
            for (int rr = 0; rr < 4; rr++) {
                int m = r + rr * 32;
                float4 av = *reinterpret_cast<const float4*>(A + m * K + k0 + c * 4);
                As[c * 4 + 0][m] = av.x;
                As[c * 4 + 1][m] = av.y;
                As[c * 4 + 2][m] = av.z;
                As[c * 4 + 3][m] = av.w;
            }
        }
        // load B tile (32x8 = 256 floats)
        if (tid < BK * BN) {
            int kk = tid / BN, n = tid % BN;
            Bs[kk][n] = W[(k0 + kk) * HL + n0 + n];
        }
        __syncthreads();

#pragma unroll
        for (int kk = 0; kk < BK; kk++) {
            const ULL* ap = reinterpret_cast<const ULL*>(&As[kk][trow * 4]);
            ULL a0 = ap[0], a1 = ap[1];
            ULL bd = dup2(Bs[kk][tcol]);
            ffma2(acc0, a0, bd);
            ffma2(acc1, a1, bd);
        }
        __syncthreads();
    }

    float v0, v1, v2, v3;
    unpack2(acc0, v0, v1);
    unpack2(acc1, v2, v3);
    int gn = n0 + tcol;
    float bb = bias[gn];
    v0 = leaky(v0 + bb); v1 = leaky(v1 + bb);
    v2 = leaky(v2 + bb); v3 = leaky(v3 + bb);
    int m = trow * 4;
    if (TRANS) {
        float4 out = make_float4(v0, v1, v2, v3);
        *reinterpret_cast<float4*>(C + gn * Bsz + m) = out;
    } else {
        C[(m + 0) * HL + gn] = v0;
        C[(m + 1) * HL + gn] = v1;
        C[(m + 2) * HL + gn] = v2;
        C[(m + 3) * HL + gn] = v3;
    }
}

// ---------------------------------------------------------------------------
// wab GEMM: C(128, 8450) = At^T(128,512) @ W(512,8450) + bias
// At is transposed A: [k][m]. BM=128, BN=64, BK=32, 3-stage cp.async pipeline.
// 256 threads; TM=8 (4 packed m-pairs), TN=4. Grid = 133 (one wave).
// ---------------------------------------------------------------------------
__global__ void __launch_bounds__(256, 1) wab_gemm(const float* __restrict__ At,
                                                   const float* __restrict__ W,
                                                   const float* __restrict__ bias,
                                                   float* __restrict__ C) {
    constexpr int BK = 32, BN = 64, S = 3, K = 512, NT = K / BK, N = OUTSZ;
    extern __shared__ float sm[];
    float* As = sm;                     // S * BK * 128 floats
    float* Bs = sm + S * BK * 128;      // S * BK * BN floats

    const int tid  = threadIdx.x;
    const int n0   = blockIdx.x * BN;
    const int tcol = tid & 15;          // 0..15, n-offset tcol*4
    const int trow = tid >> 4;          // 0..15, m-offset trow*8

    auto load_tile = [&](int t, int s) {
        // A: 32 rows x 128 floats = 1024 16B chunks / 256 threads = 4 iters
        float* Ad = As + s * BK * 128;
        const float* Ag = At + t * BK * 128;
#pragma unroll
        for (int u = 0; u < 4; u++) {
            int idx = tid + u * 256;
            int row = idx >> 5, col = (idx & 31) << 2;
            uint32_t d = (uint32_t)__cvta_generic_to_shared(Ad + row * 128 + col);
            const float* src = Ag + row * 128 + col;
            asm volatile("cp.async.cg.shared.global [%0], [%1], 16;"
                         :: "r"(d), "l"(src));
        }
        // B: 32 rows x 64 floats = 1024 8B chunks / 256 threads = 4 iters.
        // W rows only 8B-aligned -> 8B cp.async with zfill predication on tail.
        float* Bd = Bs + s * BK * BN;
#pragma unroll
        for (int u = 0; u < 4; u++) {
            int idx = tid + u * 256;
            int row = idx >> 5, c = (idx & 31) << 1;   // row 0..31, c 0..62
            int gn = n0 + c;
            uint32_t d = (uint32_t)__cvta_generic_to_shared(Bd + row * BN + c);
            const float* src = W + (size_t)(t * BK + row) * N + (gn < N ? gn : 0);
            int bytes = (gn < N) ? 8 : 0;
            asm volatile("cp.async.ca.shared.global [%0], [%1], 8, %2;"
                         :: "r"(d), "l"(src), "r"(bytes));
        }
        asm volatile("cp.async.commit_group;");
    };

    ULL acc[4][4];
#pragma unroll
    for (int i = 0; i < 4; i++)
#pragma unroll
        for (int j = 0; j < 4; j++) acc[i][j] = 0ull;

    load_tile(0, 0);
    load_tile(1, 1);

    for (int t = 0; t < NT; t++) {
        // Tail-safe wait: on the last tile no new group follows, so drain all.
        if (t + 1 < NT) asm volatile("cp.async.wait_group 1;");
        else            asm volatile("cp.async.wait_group 0;");
        __syncthreads();
        if (t + S - 1 < NT) load_tile(t + S - 1, (t + S - 1) % S);

        const float* As_ = As + (t % S) * BK * 128;
        const float* Bs_ = Bs + (t % S) * BK * BN;
#pragma unroll
        for (int kk = 0; kk < BK; kk++) {
            const ULL* ap = reinterpret_cast<const ULL*>(As_ + kk * 128 + trow * 8);
            ULL a0 = ap[0], a1 = ap[1], a2 = ap[2], a3 = ap[3];
            float4 bv = *reinterpret_cast<const float4*>(Bs_ + kk * BN + tcol * 4);
            ULL b0 = dup2(bv.x), b1 = dup2(bv.y), b2 = dup2(bv.z), b3 = dup2(bv.w);
            ffma2(acc[0][0], a0, b0); ffma2(acc[0][1], a0, b1);
            ffma2(acc[0][2], a0, b2); ffma2(acc[0][3], a0, b3);
            ffma2(acc[1][0], a1, b0); ffma2(acc[1][1], a1, b1);
            ffma2(acc[1][2], a1, b2); ffma2(acc[1][3], a1, b3);
            ffma2(acc[2][0], a2, b0); ffma2(acc[2][1], a2, b1);
            ffma2(acc[2][2], a2, b2); ffma2(acc[2][3], a2, b3);
            ffma2(acc[3][0], a3, b0); ffma2(acc[3][1], a3, b1);
            ffma2(acc[3][2], a3, b2); ffma2(acc[3][3], a3, b3);
        }
        __syncthreads();
    }

    // epilogue: acc[i][j] holds rows (trow*8+2i, trow*8+2i+1), col n0+tcol*4+j
#pragma unroll
    for (int j = 0; j < 4; j++) {
        int gn = n0 + tcol * 4 + j;
        if (gn < N) {
            float bb = bias[gn];
#pragma unroll
            for (int i = 0; i < 4; i++) {
                float lo, hi;
                unpack2(acc[i][j], lo, hi);
                int m = trow * 8 + 2 * i;
                C[(size_t)m * N + gn]       = lo + bb;
                C[(size_t)(m + 1) * N + gn] = hi + bb;
            }
        }
    }
}

// ---------------------------------------------------------------------------
// Decoder: one block per b, one thread per g. wab[b] staged into smem.
// Activations in smem rows (conflict-free via stride 65); accumulators in
// packed f32x2 register pairs; weight LDS.128 all warp-broadcast.
// ---------------------------------------------------------------------------
#define SW1 0        // 4096
#define SW2 4096     // 4096
#define SW0 8192     // 64
#define SW3 8256     // 64
#define SB1 8320     // 64
#define SB2 8384     // 64
#define SB0 8448
#define SB3 8449
#define SX  8452
#define XSTRIDE 65
#define DEC_SMEM_FLOATS (SX + 128 * XSTRIDE)
#define DEC_SMEM_BYTES  (DEC_SMEM_FLOATS * 4)

__device__ __forceinline__ void dec_layer(const float* __restrict__ s,
                                          float* __restrict__ xs,
                                          int wbase, int bbase) {
    ULL acc[32];
#pragma unroll
    for (int q = 0; q < 16; q++) {
        float4 bb = *reinterpret_cast<const float4*>(s + bbase + q * 4);
        acc[2 * q]     = pack2(bb.x, bb.y);
        acc[2 * q + 1] = pack2(bb.z, bb.w);
    }
#pragma unroll 4
    for (int i = 0; i < Dd; i++) {
        ULL vd = dup2(xs[i]);
        const ULL* wr = reinterpret_cast<const ULL*>(s + wbase + i * Dd);
#pragma unroll
        for (int q = 0; q < 32; q++) ffma2(acc[q], vd, wr[q]);
    }
#pragma unroll
    for (int q = 0; q < 32; q++) {
        float lo, hi;
        unpack2(acc[q], lo, hi);
        xs[2 * q]     = __sinf(lo);
        xs[2 * q + 1] = __sinf(hi);
    }
}

__global__ void __launch_bounds__(128) decoder_kernel(const float* __restrict__ log_P,
                                                      float* __restrict__ out) {
    extern __shared__ float s[];
    const int b = blockIdx.x;
    const int tid = threadIdx.x;
    const float* gw = g_wab + (size_t)b * OUTSZ;

    for (int i = tid; i < 4096; i += 128) s[SW1 + i] = gw[65 + i];
    for (int i = tid; i < 4096; i += 128) s[SW2 + i] = gw[4225 + i];
    if (tid < 64) {
        s[SW0 + tid] = gw[tid];
        s[SW3 + tid] = gw[8385 + tid];
        s[SB1 + tid] = gw[4161 + tid];
        s[SB2 + tid] = gw[8321 + tid];
    }
    if (tid == 0) { s[SB0] = gw[64]; s[SB3] = gw[8449]; }
    __syncthreads();

    if (tid < Gsz) {
        float x = log_P[b * Gsz + tid] * (1.f / 3.f);
        float* xs = &s[SX + tid * XSTRIDE];
        float b0 = s[SB0];
#pragma unroll
        for (int j = 0; j < Dd; j++)
            xs[j] = __sinf(30.f * fmaf(x, s[SW0 + j], b0));

        dec_layer(s, xs, SW1, SB1);
        dec_layer(s, xs, SW2, SB2);

        float accf = s[SB3];
#pragma unroll
        for (int i = 0; i < Dd; i++) accf = fmaf(xs[i], s[SW3 + i], accf);
        out[b * Gsz + tid] = fmaf(accf, 500.f, 1500.f);
    }
}

// ---------------------------------------------------------------------------
// Launch
// ---------------------------------------------------------------------------
#define WAB_SMEM_BYTES ((3 * 32 * 128 + 3 * 32 * 64) * 4)   // 72 KB

extern "C" void kernel_launch(void* const* d_in, const int* in_sizes, int n_in,
                              void* d_out, int out_size) {
    const float* z     = (const float*)d_in[0];
    const float* log_P = (const float*)d_in[1];
    const float* hW0   = (const float*)d_in[2];
    const float* hb0   = (const float*)d_in[3];
    const float* hW1   = (const float*)d_in[4];
    const float* hb1   = (const float*)d_in[5];
    const float* hW2   = (const float*)d_in[6];
    const float* hb2   = (const float*)d_in[7];
    const float* hWo   = (const float*)d_in[8];
    const float* hbo   = (const float*)d_in[9];
    float* out = (float*)d_out;

    float *h0p, *h1p, *h2tp, *wabp;
    cudaGetSymbolAddress((void**)&h0p, g_h0);
    cudaGetSymbolAddress((void**)&h1p, g_h1);
    cudaGetSymbolAddress((void**)&h2tp, g_h2t);
    cudaGetSymbolAddress((void**)&wabp, g_wab);

    cudaFuncSetAttribute(wab_gemm, cudaFuncAttributeMaxDynamicSharedMemorySize,
                         WAB_SMEM_BYTES);
    cudaFuncSetAttribute(decoder_kernel, cudaFuncAttributeMaxDynamicSharedMemorySize,
                         DEC_SMEM_BYTES);

    k_h0<<<Bsz, HL>>>(z, hW0, hb0);
    hidden_gemm<false><<<HL / 8, 256>>>(h0p, hW1, hb1, h1p);
    hidden_gemm<true ><<<HL / 8, 256>>>(h1p, hW2, hb2, h2tp);
    wab_gemm<<<(OUTSZ + 63) / 64, 256, WAB_SMEM_BYTES>>>(h2tp, hWo, hbo, wabp);
    decoder_kernel<<<Bsz, 128, DEC_SMEM_BYTES>>>(log_P, out);
}

// round 4
// speedup vs baseline: 1.6586x; 1.2662x over previous
#include <cuda_runtime.h>
#include <cuda_bf16.h>
#include <cstdint>

// Problem constants
#define Bsz   128
#define Gsz   100
#define Lz    16
#define HL    512
#define Dd    64
#define OUTSZ 8450   // 64+1 + 4096+64 + 4096+64 + 64+1

typedef unsigned long long ULL;

// Scratch (device globals: no allocation allowed). All transposed [k][m].
__device__ __align__(16) float g_h0t[HL * Bsz];
__device__ __align__(16) float g_h1t[HL * Bsz];
__device__ __align__(16) float g_h2t[HL * Bsz];
__device__ __align__(16) float g_wab[Bsz * OUTSZ];

__device__ __forceinline__ float leaky(float v) { return v > 0.f ? v : 0.01f * v; }

// ---- packed fp32x2 helpers (sm_100 packed dual-FMA; bit-exact IEEE fp32) ----
__device__ __forceinline__ ULL pack2(float lo, float hi) {
    ULL r; asm("mov.b64 %0, {%1, %2};" : "=l"(r) : "f"(lo), "f"(hi)); return r;
}
__device__ __forceinline__ ULL dup2(float x) {
    ULL r; asm("mov.b64 %0, {%1, %1};" : "=l"(r) : "f"(x)); return r;
}
__device__ __forceinline__ void unpack2(ULL v, float& lo, float& hi) {
    asm("mov.b64 {%0, %1}, %2;" : "=f"(lo), "=f"(hi) : "l"(v));
}
__device__ __forceinline__ void ffma2(ULL& acc, ULL a, ULL b) {
    asm("fma.rn.f32x2 %0, %1, %2, %0;" : "+l"(acc) : "l"(a), "l"(b));
}

// ---------------------------------------------------------------------------
// Kernel 1: h0t[j][b] = leaky(z[b] . hW0[:,j] + hb0[j])   (transposed store)
// ---------------------------------------------------------------------------
__global__ void k_h0(const float* __restrict__ z, const float* __restrict__ hW0,
                     const float* __restrict__ hb0) {
    __shared__ float zs[Lz];
    int b = blockIdx.x;
    int j = threadIdx.x;
    if (j < Lz) zs[j] = z[b * Lz + j];
    __syncthreads();
    float acc = hb0[j];
#pragma unroll
    for (int i = 0; i < Lz; i++) acc = fmaf(zs[i], hW0[i * HL + j], acc);
    g_h0t[j * Bsz + b] = leaky(acc);
}

// ---------------------------------------------------------------------------
// Hidden GEMM (pipelined, trans-A, trans-out):
//   Ct[n][m] = leaky( sum_k At[k][m] * W[k][n] + bias[n] )
// BM=128, BN=8, BK=64, S=3 stages, 256 threads, grid=64.
// ---------------------------------------------------------------------------
__global__ void __launch_bounds__(256, 1) hid_gemm(const float* __restrict__ At,
                                                   const float* __restrict__ W,
                                                   const float* __restrict__ bias,
                                                   float* __restrict__ Ct) {
    constexpr int BK = 64, BN = 8, S = 3, K = 512, NT = K / BK;
    constexpr int ASZ = BK * 128;    // 8192 floats per stage
    constexpr int BSZ = BK * BN;     // 512 floats per stage
    extern __shared__ float sm[];
    float* As = sm;                  // S * ASZ
    float* Bs = sm + S * ASZ;        // S * BSZ

    const int tid  = threadIdx.x;
    const int n0   = blockIdx.x * BN;
    const int tcol = tid & 7;        // n
    const int trow = tid >> 3;       // 0..31, m0 = trow*4
    const int m0   = trow * 4;

    auto load_tile = [&](int t, int s) {
        float* Ad = As + s * ASZ;
        const float* Ag = At + t * BK * 128;
#pragma unroll
        for (int u = 0; u < 8; u++) {
            int idx = tid + u * 256;               // 2048 16B chunks
            int row = idx >> 5, col = (idx & 31) << 2;
            uint32_t d = (uint32_t)__cvta_generic_to_shared(Ad + row * 128 + col);
            asm volatile("cp.async.cg.shared.global [%0], [%1], 16;"
                         :: "r"(d), "l"(Ag + row * 128 + col));
        }
        if (tid < 128) {                           // B: 64 rows x 2 chunks
            int row = tid >> 1, c = (tid & 1) << 2;
            float* Bd = Bs + s * BSZ;
            uint32_t d = (uint32_t)__cvta_generic_to_shared(Bd + row * BN + c);
            asm volatile("cp.async.ca.shared.global [%0], [%1], 16;"
                         :: "r"(d), "l"(W + (size_t)(t * BK + row) * HL + n0 + c));
        }
        asm volatile("cp.async.commit_group;");
    };

    ULL acc0 = 0, acc1 = 0;
    load_tile(0, 0);
    load_tile(1, 1);

    for (int t = 0; t < NT; t++) {
        if (t + 1 < NT) asm volatile("cp.async.wait_group 1;");
        else            asm volatile("cp.async.wait_group 0;");
        __syncthreads();
        if (t + 2 < NT) load_tile(t + 2, (t + 2) % S);

        const float* As_ = As + (t % S) * ASZ;
        const float* Bs_ = Bs + (t % S) * BSZ;
#pragma unroll
        for (int kk = 0; kk < BK; kk++) {
            const ULL* ap = reinterpret_cast<const ULL*>(As_ + kk * 128 + m0);
            ULL a0 = ap[0], a1 = ap[1];
            ULL bd = dup2(Bs_[kk * BN + tcol]);
            ffma2(acc0, a0, bd);
            ffma2(acc1, a1, bd);
        }
        __syncthreads();
    }

    float v0, v1, v2, v3;
    unpack2(acc0, v0, v1);
    unpack2(acc1, v2, v3);
    int gn = n0 + tcol;
    float bb = bias[gn];
    float4 out = make_float4(leaky(v0 + bb), leaky(v1 + bb),
                             leaky(v2 + bb), leaky(v3 + bb));
    *reinterpret_cast<float4*>(Ct + gn * Bsz + m0) = out;
}
#define HID_SMEM_BYTES ((3 * (64 * 128) + 3 * (64 * 8)) * 4)   // ~102 KB

// ---------------------------------------------------------------------------
// wab GEMM: C(128, 8450) = At^T(128,512) @ W(512,8450) + bias
// At transposed [k][m]. BM=128, BN=64, BK=32, S=4 cp.async pipeline.
// 256 threads; TM=8 (4 packed m-pairs), TN=4. Grid = 133 (one wave).
// ---------------------------------------------------------------------------
__global__ void __launch_bounds__(256, 1) wab_gemm(const float* __restrict__ At,
                                                   const float* __restrict__ W,
                                                   const float* __restrict__ bias,
                                                   float* __restrict__ C) {
    constexpr int BK = 32, BN = 64, S = 4, K = 512, NT = K / BK, N = OUTSZ;
    constexpr int ASZ = BK * 128, BSZ = BK * BN;
    extern __shared__ float sm[];
    float* As = sm;
    float* Bs = sm + S * ASZ;

    const int tid  = threadIdx.x;
    const int n0   = blockIdx.x * BN;
    const int tcol = tid & 15;          // n-offset tcol*4
    const int trow = tid >> 4;          // m-offset trow*8

    auto load_tile = [&](int t, int s) {
        float* Ad = As + s * ASZ;
        const float* Ag = At + t * BK * 128;
#pragma unroll
        for (int u = 0; u < 4; u++) {
            int idx = tid + u * 256;               // 1024 16B chunks
            int row = idx >> 5, col = (idx & 31) << 2;
            uint32_t d = (uint32_t)__cvta_generic_to_shared(Ad + row * 128 + col);
            asm volatile("cp.async.cg.shared.global [%0], [%1], 16;"
                         :: "r"(d), "l"(Ag + row * 128 + col));
        }
        // B: 32 rows x 64 floats = 1024 8B chunks (W rows only 8B-aligned)
        float* Bd = Bs + s * BSZ;
#pragma unroll
        for (int u = 0; u < 4; u++) {
            int idx = tid + u * 256;
            int row = idx >> 5, c = (idx & 31) << 1;
            int gn = n0 + c;
            uint32_t d = (uint32_t)__cvta_generic_to_shared(Bd + row * BN + c);
            const float* src = W + (size_t)(t * BK + row) * N + (gn < N ? gn : 0);
            int bytes = (gn < N) ? 8 : 0;
            asm volatile("cp.async.ca.shared.global [%0], [%1], 8, %2;"
                         :: "r"(d), "l"(src), "r"(bytes));
        }
        asm volatile("cp.async.commit_group;");
    };

    ULL acc[4][4];
#pragma unroll
    for (int i = 0; i < 4; i++)
#pragma unroll
        for (int j = 0; j < 4; j++) acc[i][j] = 0ull;

    load_tile(0, 0);
    load_tile(1, 1);
    load_tile(2, 2);

    for (int t = 0; t < NT; t++) {
        int rem = NT - 1 - t;           // commits still to come after this iter's
        if (rem >= 2)      asm volatile("cp.async.wait_group 2;");
        else if (rem == 1) asm volatile("cp.async.wait_group 1;");
        else               asm volatile("cp.async.wait_group 0;");
        __syncthreads();
        if (t + S - 1 < NT) load_tile(t + S - 1, (t + S - 1) % S);

        const float* As_ = As + (t % S) * ASZ;
        const float* Bs_ = Bs + (t % S) * BSZ;
#pragma unroll
        for (int kk = 0; kk < BK; kk++) {
            const ULL* ap = reinterpret_cast<const ULL*>(As_ + kk * 128 + trow * 8);
            ULL a0 = ap[0], a1 = ap[1], a2 = ap[2], a3 = ap[3];
            float4 bv = *reinterpret_cast<const float4*>(Bs_ + kk * BN + tcol * 4);
            ULL b0 = dup2(bv.x), b1 = dup2(bv.y), b2 = dup2(bv.z), b3 = dup2(bv.w);
            ffma2(acc[0][0], a0, b0); ffma2(acc[0][1], a0, b1);
            ffma2(acc[0][2], a0, b2); ffma2(acc[0][3], a0, b3);
            ffma2(acc[1][0], a1, b0); ffma2(acc[1][1], a1, b1);
            ffma2(acc[1][2], a1, b2); ffma2(acc[1][3], a1, b3);
            ffma2(acc[2][0], a2, b0); ffma2(acc[2][1], a2, b1);
            ffma2(acc[2][2], a2, b2); ffma2(acc[2][3], a2, b3);
            ffma2(acc[3][0], a3, b0); ffma2(acc[3][1], a3, b1);
            ffma2(acc[3][2], a3, b2); ffma2(acc[3][3], a3, b3);
        }
        __syncthreads();
    }

#pragma unroll
    for (int j = 0; j < 4; j++) {
        int gn = n0 + tcol * 4 + j;
        if (gn < N) {
            float bb = bias[gn];
#pragma unroll
            for (int i = 0; i < 4; i++) {
                float lo, hi;
                unpack2(acc[i][j], lo, hi);
                int m = trow * 8 + 2 * i;
                C[(size_t)m * N + gn]       = lo + bb;
                C[(size_t)(m + 1) * N + gn] = hi + bb;
            }
        }
    }
}
#define WAB_SMEM_BYTES ((4 * 32 * 128 + 4 * 32 * 64) * 4)   // 96 KB

// ---------------------------------------------------------------------------
// Decoder: one block per b, one thread per g. wab[b] staged into smem.
// ---------------------------------------------------------------------------
#define SW1 0        // 4096
#define SW2 4096     // 4096
#define SW0 8192     // 64
#define SW3 8256     // 64
#define SB1 8320     // 64
#define SB2 8384     // 64
#define SB0 8448
#define SB3 8449
#define SX  8452
#define XSTRIDE 65
#define DEC_SMEM_FLOATS (SX + 128 * XSTRIDE)
#define DEC_SMEM_BYTES  (DEC_SMEM_FLOATS * 4)

__device__ __forceinline__ void dec_layer(const float* __restrict__ s,
                                          float* __restrict__ xs,
                                          int wbase, int bbase) {
    ULL acc[32];
#pragma unroll
    for (int q = 0; q < 16; q++) {
        float4 bb = *reinterpret_cast<const float4*>(s + bbase + q * 4);
        acc[2 * q]     = pack2(bb.x, bb.y);
        acc[2 * q + 1] = pack2(bb.z, bb.w);
    }
#pragma unroll 4
    for (int i = 0; i < Dd; i++) {
        ULL vd = dup2(xs[i]);
        const ULL* wr = reinterpret_cast<const ULL*>(s + wbase + i * Dd);
#pragma unroll
        for (int q = 0; q < 32; q++) ffma2(acc[q], vd, wr[q]);
    }
#pragma unroll
    for (int q = 0; q < 32; q++) {
        float lo, hi;
        unpack2(acc[q], lo, hi);
        xs[2 * q]     = __sinf(lo);
        xs[2 * q + 1] = __sinf(hi);
    }
}

__global__ void __launch_bounds__(128) decoder_kernel(const float* __restrict__ log_P,
                                                      float* __restrict__ out) {
    extern __shared__ float s[];
    const int b = blockIdx.x;
    const int tid = threadIdx.x;
    const float* gw = g_wab + (size_t)b * OUTSZ;

    for (int i = tid; i < 4096; i += 128) s[SW1 + i] = gw[65 + i];
    for (int i = tid; i < 4096; i += 128) s[SW2 + i] = gw[4225 + i];
    if (tid < 64) {
        s[SW0 + tid] = gw[tid];
        s[SW3 + tid] = gw[8385 + tid];
        s[SB1 + tid] = gw[4161 + tid];
        s[SB2 + tid] = gw[8321 + tid];
    }
    if (tid == 0) { s[SB0] = gw[64]; s[SB3] = gw[8449]; }
    __syncthreads();

    if (tid < Gsz) {
        float x = log_P[b * Gsz + tid] * (1.f / 3.f);
        float* xs = &s[SX + tid * XSTRIDE];
        float b0 = s[SB0];
#pragma unroll
        for (int j = 0; j < Dd; j++)
            xs[j] = __sinf(30.f * fmaf(x, s[SW0 + j], b0));

        dec_layer(s, xs, SW1, SB1);
        dec_layer(s, xs, SW2, SB2);

        float accf = s[SB3];
#pragma unroll
        for (int i = 0; i < Dd; i++) accf = fmaf(xs[i], s[SW3 + i], accf);
        out[b * Gsz + tid] = fmaf(accf, 500.f, 1500.f);
    }
}

// ---------------------------------------------------------------------------
// Launch
// ---------------------------------------------------------------------------
extern "C" void kernel_launch(void* const* d_in, const int* in_sizes, int n_in,
                              void* d_out, int out_size) {
    const float* z     = (const float*)d_in[0];
    const float* log_P = (const float*)d_in[1];
    const float* hW0   = (const float*)d_in[2];
    const float* hb0   = (const float*)d_in[3];
    const float* hW1   = (const float*)d_in[4];
    const float* hb1   = (const float*)d_in[5];
    const float* hW2   = (const float*)d_in[6];
    const float* hb2   = (const float*)d_in[7];
    const float* hWo   = (const float*)d_in[8];
    const float* hbo   = (const float*)d_in[9];
    float* out = (float*)d_out;

    float *h0tp, *h1tp, *h2tp, *wabp;
    cudaGetSymbolAddress((void**)&h0tp, g_h0t);
    cudaGetSymbolAddress((void**)&h1tp, g_h1t);
    cudaGetSymbolAddress((void**)&h2tp, g_h2t);
    cudaGetSymbolAddress((void**)&wabp, g_wab);

    cudaFuncSetAttribute(hid_gemm, cudaFuncAttributeMaxDynamicSharedMemorySize,
                         HID_SMEM_BYTES);
    cudaFuncSetAttribute(wab_gemm, cudaFuncAttributeMaxDynamicSharedMemorySize,
                         WAB_SMEM_BYTES);
    cudaFuncSetAttribute(decoder_kernel, cudaFuncAttributeMaxDynamicSharedMemorySize,
                         DEC_SMEM_BYTES);

    k_h0<<<Bsz, HL>>>(z, hW0, hb0);
    hid_gemm<<<HL / 8, 256, HID_SMEM_BYTES>>>(h0tp, hW1, hb1, h1tp);
    hid_gemm<<<HL / 8, 256, HID_SMEM_BYTES>>>(h1tp, hW2, hb2, h2tp);
    wab_gemm<<<(OUTSZ + 63) / 64, 256, WAB_SMEM_BYTES>>>(h2tp, hWo, hbo, wabp);
    decoder_kernel<<<Bsz, 128, DEC_SMEM_BYTES>>>(log_P, out);
}